// round 8
// baseline (speedup 1.0000x reference)
#include <cuda_runtime.h>
#include <cstdint>
#include <cstddef>

// ---------------------------------------------------------------------------
// Monarch-like two-stage block-diagonal interconnect, softmax-gated.
//   conn1 = softmax(c1*3, axis=i)   c1: [128][64][64]  ([n][i][m])
//   conn2 = softmax(c2*3, axis=n)   c2: [64][128][128] ([m][n][o])
//   t[b,n,m]   = sum_i x[b, n*64+i] * conn1[n,i,m]
//   out[b,m,o] = sum_n t[b,n,m]     * conn2[m,n,o]
// t materialized transposed: t2[b][m][n] (coalesced stage-2 reads).
// Weights + t pre-rounded to tf32 -> consumers cp.async raw bits to MMA.
// Bank-conflict rule: A-pattern loads (row varies with g) need stride%32==4;
// B-pattern loads (row varies with tg) need stride%32==8.
// ---------------------------------------------------------------------------

#define HID     8192
#define NB1     128
#define I1      64
#define M1      64
#define NB2     64
#define I2      128
#define O2      128
#define MAXB    4096

__device__ float g_conn1[NB1 * I1 * M1];      // [n][i][m]  (tf32-rounded)
__device__ float g_conn2[NB2 * I2 * O2];      // [m][n][o]  (tf32-rounded)
__device__ float g_t[(size_t)MAXB * HID];     // t2: [b][m][n] (tf32-rounded)

// ---------------------------------------------------------------------------
// helpers
// ---------------------------------------------------------------------------
__device__ __forceinline__ unsigned f2tf(float f) {
    unsigned u;
    asm("cvt.rna.tf32.f32 %0, %1;" : "=r"(u) : "f"(f));
    return u;
}

__device__ __forceinline__ void mma_tf32(float* d,
                                         unsigned a0, unsigned a1,
                                         unsigned a2, unsigned a3,
                                         unsigned b0, unsigned b1) {
    asm volatile(
        "mma.sync.aligned.m16n8k8.row.col.f32.tf32.tf32.f32 "
        "{%0,%1,%2,%3}, {%4,%5,%6,%7}, {%8,%9}, {%0,%1,%2,%3};\n"
        : "+f"(d[0]), "+f"(d[1]), "+f"(d[2]), "+f"(d[3])
        : "r"(a0), "r"(a1), "r"(a2), "r"(a3), "r"(b0), "r"(b1));
}

__device__ __forceinline__ void cp16(unsigned smem_addr, const void* gptr) {
    asm volatile("cp.async.cg.shared.global [%0], [%1], 16;"
                 :: "r"(smem_addr), "l"(gptr));
}
__device__ __forceinline__ void cp_commit() {
    asm volatile("cp.async.commit_group;");
}
template <int N> __device__ __forceinline__ void cp_wait() {
    asm volatile("cp.async.wait_group %0;" :: "n"(N));
}

// ---------------------------------------------------------------------------
// Softmax precompute: ONE global read pass (column cached in registers),
// 128 blocks x 128 threads for full-chip spread. Outputs tf32-rounded.
// ---------------------------------------------------------------------------
__global__ void __launch_bounds__(128)
softmax_kernel(const float* __restrict__ c1, const float* __restrict__ c2) {
    int gid = blockIdx.x * blockDim.x + threadIdx.x;   // 16384
    if (gid < NB1 * M1) {
        int n = gid >> 6, m = gid & 63;
        const float* p = c1 + (size_t)n * (I1 * M1) + m;
        float v[I1];
        float mx = -1e30f;
        #pragma unroll
        for (int i = 0; i < I1; i++) {
            v[i] = p[i * M1] * 3.0f;
            mx = fmaxf(mx, v[i]);
        }
        float s = 0.0f;
        #pragma unroll
        for (int i = 0; i < I1; i++) {
            v[i] = expf(v[i] - mx);
            s += v[i];
        }
        float inv = 1.0f / s;
        float* q = g_conn1 + (size_t)n * (I1 * M1) + m;
        #pragma unroll
        for (int i = 0; i < I1; i++)
            q[i * M1] = __uint_as_float(f2tf(v[i] * inv));
    } else {
        int idx = gid - NB1 * M1;
        int m = idx >> 7, o = idx & 127;
        const float* p = c2 + (size_t)m * (I2 * O2) + o;
        float v[I2];
        float mx = -1e30f;
        #pragma unroll
        for (int i = 0; i < I2; i++) {
            v[i] = p[i * O2] * 3.0f;
            mx = fmaxf(mx, v[i]);
        }
        float s = 0.0f;
        #pragma unroll
        for (int i = 0; i < I2; i++) {
            v[i] = expf(v[i] - mx);
            s += v[i];
        }
        float inv = 1.0f / s;
        float* q = g_conn2 + (size_t)m * (I2 * O2) + o;
        #pragma unroll
        for (int i = 0; i < I2; i++)
            q[i * O2] = __uint_as_float(f2tf(v[i] * inv));
    }
}

// ---------------------------------------------------------------------------
// Stage 1: CTA = (64-row btile, group of 8 n-blocks). 512 threads, 16 warps.
// Pipeline: group k = (x chunk k, conn1 block k); 4-slot conn ring, issue
// distance 3, one barrier per iteration. nl processed in TWO HALVES of 4 so
// live accumulators stay at 32 regs (no spills under the 128-reg cap);
// each half ends with a 16B-per-(b,m) epilogue (n chunk of 4 contiguous).
// smem: xs raw fp32 [64][516] + cs tf32 [4][64][72] -> 205,824 B
// XS_STR%32==4 (A-pattern conflict-free), CS_STR%32==8 (B-pattern).
// ---------------------------------------------------------------------------
#define S1_BT    64
#define XS_STR   516
#define CS_STR   72
#define CS_SLOTS 4
#define SMEM1    ((S1_BT * XS_STR + CS_SLOTS * I1 * CS_STR) * 4)

__global__ void __launch_bounds__(512, 1)
stage1_kernel(const float* __restrict__ x) {
    extern __shared__ unsigned char smem_raw[];
    float*    xs = (float*)smem_raw;                    // [64][516]
    unsigned* cs = (unsigned*)(xs + S1_BT * XS_STR);    // [4][64][72]

    const int tid = threadIdx.x;
    const int bt  = blockIdx.x;
    const int nh  = blockIdx.y;            // 0..15
    const int b0  = bt * S1_BT;

    const unsigned xs_base = (unsigned)__cvta_generic_to_shared(xs);
    const unsigned cs_base = (unsigned)__cvta_generic_to_shared(cs);

    auto issue_group = [&](int k) {
        for (int c = tid; c < S1_BT * 16; c += 512) {
            int row = c >> 4, c4 = c & 15;
            const float* src = x + (size_t)(b0 + row) * HID
                                 + (size_t)nh * 512 + k * 64 + c4 * 4;
            cp16(xs_base + (unsigned)(row * XS_STR + k * 64 + c4 * 4) * 4, src);
        }
        int n = nh * 8 + k, slot = k & (CS_SLOTS - 1);
        for (int c = tid; c < I1 * 16; c += 512) {
            int i = c >> 4, c4 = c & 15;
            const float* src = g_conn1 + (size_t)n * (I1 * M1) + i * M1 + c4 * 4;
            cp16(cs_base + (unsigned)(slot * I1 * CS_STR + i * CS_STR + c4 * 4) * 4,
                 src);
        }
        cp_commit();
    };

    issue_group(0);
    issue_group(1);
    issue_group(2);

    const int w    = tid >> 5;
    const int lane = tid & 31;
    const int g    = lane >> 2;
    const int tg   = lane & 3;
    const int brow = w >> 2;   // 0..3 -> rows 16*brow
    const int mcol = w & 3;    // 0..3 -> m base 16*mcol

    #pragma unroll
    for (int h = 0; h < 2; h++) {
        float acc[4][2][4] = {};
        #pragma unroll
        for (int q = 0; q < 4; q++) {
            const int nl = h * 4 + q;
            if (nl < 6)       cp_wait<2>();
            else if (nl == 6) cp_wait<1>();
            else              cp_wait<0>();
            __syncthreads();
            if (nl + 3 < 8) issue_group(nl + 3);

            const unsigned* csl = cs + (nl & (CS_SLOTS - 1)) * I1 * CS_STR;
            #pragma unroll
            for (int ks = 0; ks < 8; ks++) {
                const int xc = nl * 64 + ks * 8 + tg;
                const int r  = brow * 16 + g;
                unsigned a0 = f2tf(xs[r * XS_STR + xc]);
                unsigned a1 = f2tf(xs[(r + 8) * XS_STR + xc]);
                unsigned a2 = f2tf(xs[r * XS_STR + xc + 4]);
                unsigned a3 = f2tf(xs[(r + 8) * XS_STR + xc + 4]);
                const int ck = ks * 8 + tg;
                #pragma unroll
                for (int j = 0; j < 2; j++) {
                    int mm = mcol * 16 + j * 8 + g;
                    mma_tf32(acc[q][j], a0, a1, a2, a3,
                             csl[ck * CS_STR + mm], csl[(ck + 4) * CS_STR + mm]);
                }
            }
        }

        // Half-epilogue: t2[b0+row][mm][nh*8 + h*4 .. +3], one float4 each.
        const int rbase = brow * 16 + g;
        #pragma unroll
        for (int j = 0; j < 2; j++) {
            #pragma unroll
            for (int rs = 0; rs < 2; rs++) {
                #pragma unroll
                for (int ms = 0; ms < 2; ms++) {
                    const int row = rbase + rs * 8;
                    const int mm  = mcol * 16 + j * 8 + 2 * tg + ms;
                    const int e   = rs * 2 + ms;
                    float4 v;
                    v.x = __uint_as_float(f2tf(acc[0][j][e]));
                    v.y = __uint_as_float(f2tf(acc[1][j][e]));
                    v.z = __uint_as_float(f2tf(acc[2][j][e]));
                    v.w = __uint_as_float(f2tf(acc[3][j][e]));
                    *(float4*)(g_t + (size_t)(b0 + row) * HID
                                   + mm * 128 + nh * 8 + h * 4) = v;
                }
            }
        }
    }
}

// ---------------------------------------------------------------------------
// Stage 2: CTA = (m-block, group of 2 btiles). 512 threads. Bs (conn2[m])
// loaded once; both A tiles prefetched in prologue. grid = 16 x 64 = 1024.
// As stride 132 (%32==4, A-pattern conflict-free); Bs stride 136 (%32==8).
// smem: Ab [2][128][132] + Bs [128][136] -> 204,800 B
// ---------------------------------------------------------------------------
#define ASTR_A  132
#define ASTR_B  136
#define NG2     16
#define SMEM2   ((2 * 128 * ASTR_A + 128 * ASTR_B) * 4)

__global__ void __launch_bounds__(512, 1)
stage2_kernel(float* __restrict__ out, int B) {
    extern __shared__ unsigned char smem_raw[];
    unsigned* Ab = (unsigned*)smem_raw;           // [2][128][132]
    unsigned* Bs = Ab + 2 * 128 * ASTR_A;         // [128][136]

    const int tid = threadIdx.x;
    const int m   = blockIdx.y;
    const int nb  = B / 128 / NG2;                // 2

    const unsigned ab_base = (unsigned)__cvta_generic_to_shared(Ab);
    const unsigned bs_base = (unsigned)__cvta_generic_to_shared(Bs);

    auto issue_A = [&](int k) {
        const int b0   = (blockIdx.x * nb + k) * 128;
        const int slot = k & 1;
        for (int c = tid; c < 128 * 32; c += 512) {
            int row = c >> 5, c4 = c & 31;
            cp16(ab_base + (unsigned)(slot * 128 * ASTR_A + row * ASTR_A + c4 * 4) * 4,
                 g_t + (size_t)(b0 + row) * HID + m * 128 + c4 * 4);
        }
        cp_commit();
    };

    // Prologue: Bs + A(0) in group 0, A(1) in group 1.
    for (int c = tid; c < 128 * 32; c += 512) {
        int row = c >> 5, c4 = c & 31;
        cp16(bs_base + (unsigned)(row * ASTR_B + c4 * 4) * 4,
             g_conn2 + (size_t)m * (I2 * O2) + row * O2 + c4 * 4);
    }
    issue_A(0);
    issue_A(1);

    const int w    = tid >> 5;
    const int lane = tid & 31;
    const int g    = lane >> 2;
    const int tg   = lane & 3;
    const int brow = w & 3;    // rows base 32*brow
    const int ocol = w >> 2;   // o base 32*ocol

    #pragma unroll
    for (int k = 0; k < 2; k++) {
        if (k == 0) cp_wait<1>();
        else        cp_wait<0>();
        __syncthreads();

        const unsigned* As = Ab + (k & 1) * 128 * ASTR_A;
        float acc[2][4][4] = {};
        #pragma unroll
        for (int ks = 0; ks < 16; ks++) {
            const int k0 = ks * 8;
            unsigned a[2][4];
            #pragma unroll
            for (int rt = 0; rt < 2; rt++) {
                int r = brow * 32 + rt * 16 + g;
                a[rt][0] = As[r * ASTR_A + k0 + tg];
                a[rt][1] = As[(r + 8) * ASTR_A + k0 + tg];
                a[rt][2] = As[r * ASTR_A + k0 + 4 + tg];
                a[rt][3] = As[(r + 8) * ASTR_A + k0 + 4 + tg];
            }
            #pragma unroll
            for (int ct = 0; ct < 4; ct++) {
                int o = ocol * 32 + ct * 8 + g;
                unsigned b0v = Bs[(k0 + tg) * ASTR_B + o];
                unsigned b1v = Bs[(k0 + 4 + tg) * ASTR_B + o];
                #pragma unroll
                for (int rt = 0; rt < 2; rt++)
                    mma_tf32(acc[rt][ct], a[rt][0], a[rt][1], a[rt][2], a[rt][3],
                             b0v, b1v);
            }
        }

        const int b0 = (blockIdx.x * nb + k) * 128;
        #pragma unroll
        for (int rt = 0; rt < 2; rt++) {
            int r = b0 + brow * 32 + rt * 16 + g;
            #pragma unroll
            for (int ct = 0; ct < 4; ct++) {
                int o = m * 128 + ocol * 32 + ct * 8 + 2 * tg;
                *(float2*)(out + (size_t)r * HID + o) =
                    make_float2(acc[rt][ct][0], acc[rt][ct][1]);
                *(float2*)(out + (size_t)(r + 8) * HID + o) =
                    make_float2(acc[rt][ct][2], acc[rt][ct][3]);
            }
        }
    }
}

// ---------------------------------------------------------------------------
// launch
// ---------------------------------------------------------------------------
extern "C" void kernel_launch(void* const* d_in, const int* in_sizes, int n_in,
                              void* d_out, int out_size) {
    const float* x  = (const float*)d_in[0];
    const float* c1 = (const float*)d_in[1];
    const float* c2 = (const float*)d_in[2];
    float* out = (float*)d_out;
    const int B = in_sizes[0] / HID;   // 4096

    cudaFuncSetAttribute(stage1_kernel,
                         cudaFuncAttributeMaxDynamicSharedMemorySize, SMEM1);
    cudaFuncSetAttribute(stage2_kernel,
                         cudaFuncAttributeMaxDynamicSharedMemorySize, SMEM2);

    softmax_kernel<<<(NB1 * M1 + NB2 * O2) / 128, 128>>>(c1, c2);
    stage1_kernel<<<dim3(B / S1_BT, 16), 512, SMEM1>>>(x);
    stage2_kernel<<<dim3(NG2, NB2), 512, SMEM2>>>(out, B);
}

// round 13
// speedup vs baseline: 1.9922x; 1.9922x over previous
#include <cuda_runtime.h>
#include <cuda_fp16.h>
#include <cstdint>
#include <cstddef>

// ---------------------------------------------------------------------------
// Monarch-like two-stage block-diagonal interconnect, softmax-gated.
//   conn1 = softmax(c1*3, axis=i)   c1: [128][64][64]  ([n][i][m])
//   conn2 = softmax(c2*3, axis=n)   c2: [64][128][128] ([m][n][o])
//   t[b,n,m]   = sum_i x[b, n*64+i] * conn1[n,i,m]
//   out[b,m,o] = sum_n t[b,n,m]     * conn2[m,n,o]
//
// Full fp16 datapath (same 10-bit mantissa as tf32 -> same accuracy budget),
// fp32 accumulation via mma.m16n8k16. t materialized fp16 transposed
// t2[b][m][n]. conn matrices stored TRANSPOSED fp16 so B-fragments are
// contiguous half2 loads:  g_conn1h[n][m][i],  g_conn2h[m][o][n].
// 2 CTAs/SM in both stages for latency overlap.
// ---------------------------------------------------------------------------

#define HID     8192
#define NB1     128
#define I1      64
#define M1      64
#define NB2     64
#define I2      128
#define O2      128
#define MAXB    4096

__device__ __half g_conn1h[NB1 * M1 * I1];      // [n][m][i]
__device__ __half g_conn2h[NB2 * O2 * I2];      // [m][o][n]
__device__ __half g_th[(size_t)MAXB * HID];     // t2: [b][m][n]

// ---------------------------------------------------------------------------
// helpers
// ---------------------------------------------------------------------------
__device__ __forceinline__ unsigned pack_h2(float lo, float hi) {
    unsigned u;
    asm("cvt.rn.f16x2.f32 %0, %1, %2;" : "=r"(u) : "f"(hi), "f"(lo));
    return u;
}

__device__ __forceinline__ void mma_f16(float* d,
                                        unsigned a0, unsigned a1,
                                        unsigned a2, unsigned a3,
                                        unsigned b0, unsigned b1) {
    asm volatile(
        "mma.sync.aligned.m16n8k16.row.col.f32.f16.f16.f32 "
        "{%0,%1,%2,%3}, {%4,%5,%6,%7}, {%8,%9}, {%0,%1,%2,%3};\n"
        : "+f"(d[0]), "+f"(d[1]), "+f"(d[2]), "+f"(d[3])
        : "r"(a0), "r"(a1), "r"(a2), "r"(a3), "r"(b0), "r"(b1));
}

__device__ __forceinline__ void cp16(unsigned smem_addr, const void* gptr) {
    asm volatile("cp.async.cg.shared.global [%0], [%1], 16;"
                 :: "r"(smem_addr), "l"(gptr));
}
__device__ __forceinline__ void cp_commit() {
    asm volatile("cp.async.commit_group;");
}
template <int N> __device__ __forceinline__ void cp_wait() {
    asm volatile("cp.async.wait_group %0;" :: "n"(N));
}

// ---------------------------------------------------------------------------
// Softmax precompute: one global read pass, column in registers, fp16
// TRANSPOSED outputs (each thread owns a contiguous output row).
// ---------------------------------------------------------------------------
__global__ void __launch_bounds__(128)
softmax_kernel(const float* __restrict__ c1, const float* __restrict__ c2) {
    int gid = blockIdx.x * blockDim.x + threadIdx.x;   // 16384
    if (gid < NB1 * M1) {
        int n = gid >> 6, m = gid & 63;
        const float* p = c1 + (size_t)n * (I1 * M1) + m;
        float v[I1];
        float mx = -1e30f;
        #pragma unroll
        for (int i = 0; i < I1; i++) {
            v[i] = p[i * M1] * 3.0f;
            mx = fmaxf(mx, v[i]);
        }
        float s = 0.0f;
        #pragma unroll
        for (int i = 0; i < I1; i++) {
            v[i] = expf(v[i] - mx);
            s += v[i];
        }
        float inv = 1.0f / s;
        unsigned u[I1 / 2];
        #pragma unroll
        for (int i = 0; i < I1 / 2; i++)
            u[i] = pack_h2(v[2 * i] * inv, v[2 * i + 1] * inv);
        uint4* q = (uint4*)(g_conn1h + ((size_t)n * M1 + m) * I1);
        #pragma unroll
        for (int i = 0; i < I1 / 8; i++)
            q[i] = make_uint4(u[4 * i], u[4 * i + 1], u[4 * i + 2], u[4 * i + 3]);
    } else {
        int idx = gid - NB1 * M1;
        int m = idx >> 7, o = idx & 127;
        const float* p = c2 + (size_t)m * (I2 * O2) + o;
        float v[I2];
        float mx = -1e30f;
        #pragma unroll
        for (int i = 0; i < I2; i++) {
            v[i] = p[i * O2] * 3.0f;
            mx = fmaxf(mx, v[i]);
        }
        float s = 0.0f;
        #pragma unroll
        for (int i = 0; i < I2; i++) {
            v[i] = expf(v[i] - mx);
            s += v[i];
        }
        float inv = 1.0f / s;
        unsigned u[I2 / 2];
        #pragma unroll
        for (int i = 0; i < I2 / 2; i++)
            u[i] = pack_h2(v[2 * i] * inv, v[2 * i + 1] * inv);
        uint4* q = (uint4*)(g_conn2h + ((size_t)m * O2 + o) * I2);
        #pragma unroll
        for (int i = 0; i < I2 / 8; i++)
            q[i] = make_uint4(u[4 * i], u[4 * i + 1], u[4 * i + 2], u[4 * i + 3]);
    }
}

// ---------------------------------------------------------------------------
// Stage 1: CTA = (32-row btile, group of 8 n-blocks). 256 threads, 8 warps,
// 2 CTAs/SM. x kept fp32 in smem (A-frags via LDS.64 + cvt.rn.f16x2);
// conn1h fp16 in a 4-slot ring, prefetch distance 3, one barrier/iter.
// All 8 nl accumulators in registers (acc[8][2][4] = 64 regs).
// smem: xs f32 [32][520] (66,560B) + cst f16 [4][64][72] (36,864B) = 103,424B
// Conflict-free: XS_STR%32==8 (float2 A-loads), CST_STR bytes%128==16.
// ---------------------------------------------------------------------------
#define S1_BT    32
#define XS_STR   520
#define CST_STR  72
#define CS_SLOTS 4
#define SMEM1    (S1_BT * XS_STR * 4 + CS_SLOTS * M1 * CST_STR * 2)

__global__ void __launch_bounds__(256, 2)
stage1_kernel(const float* __restrict__ x) {
    extern __shared__ unsigned char smem_raw[];
    float*  xs  = (float*)smem_raw;                       // [32][520]
    __half* cst = (__half*)(xs + S1_BT * XS_STR);         // [4][64][72]

    const int tid = threadIdx.x;
    const int bt  = blockIdx.x;
    const int nh  = blockIdx.y;            // 0..15
    const int b0  = bt * S1_BT;

    const unsigned xs_base  = (unsigned)__cvta_generic_to_shared(xs);
    const unsigned cst_base = (unsigned)__cvta_generic_to_shared(cst);

    auto issue_group = [&](int k) {
        // x chunk k: 32 rows x 64 floats (16 B x 4 per row)
        #pragma unroll
        for (int j = 0; j < 2; j++) {
            int c = tid + j * 256;          // 512 chunks
            int row = c >> 4, c4 = c & 15;
            const float* src = x + (size_t)(b0 + row) * HID
                                 + (size_t)nh * 512 + k * 64 + c4 * 4;
            cp16(xs_base + (unsigned)(row * XS_STR + k * 64 + c4 * 4) * 4, src);
        }
        // conn1h block nh*8+k -> ring slot: 64 m-rows x 128B
        int n = nh * 8 + k, slot = k & (CS_SLOTS - 1);
        #pragma unroll
        for (int j = 0; j < 2; j++) {
            int c = tid + j * 256;          // 512 chunks
            int row = c >> 3, c8 = c & 7;
            const __half* src = g_conn1h + ((size_t)n * M1 + row) * I1 + c8 * 8;
            cp16(cst_base + (unsigned)(slot * M1 * CST_STR + row * CST_STR + c8 * 8) * 2,
                 src);
        }
        cp_commit();
    };

    issue_group(0);
    issue_group(1);
    issue_group(2);

    const int w    = tid >> 5;
    const int lane = tid & 31;
    const int g    = lane >> 2;
    const int tg   = lane & 3;
    const int brow = w >> 2;   // 0..1 -> rows 16*brow
    const int mcol = w & 3;    // 0..3 -> m base 16*mcol

    float acc[8][2][4] = {};

    #pragma unroll
    for (int nl = 0; nl < 8; nl++) {
        if (nl < 6)       cp_wait<2>();
        else if (nl == 6) cp_wait<1>();
        else              cp_wait<0>();
        __syncthreads();
        if (nl + 3 < 8) issue_group(nl + 3);

        const __half* csl = cst + (nl & (CS_SLOTS - 1)) * M1 * CST_STR;
        #pragma unroll
        for (int ks = 0; ks < 4; ks++) {            // k = 16 per MMA
            const int xc = nl * 64 + ks * 16 + 2 * tg;
            const int r  = brow * 16 + g;
            float2 f0 = *(const float2*)&xs[r * XS_STR + xc];
            float2 f1 = *(const float2*)&xs[(r + 8) * XS_STR + xc];
            float2 f2 = *(const float2*)&xs[r * XS_STR + xc + 8];
            float2 f3 = *(const float2*)&xs[(r + 8) * XS_STR + xc + 8];
            unsigned a0 = pack_h2(f0.x, f0.y);
            unsigned a1 = pack_h2(f1.x, f1.y);
            unsigned a2 = pack_h2(f2.x, f2.y);
            unsigned a3 = pack_h2(f3.x, f3.y);
            #pragma unroll
            for (int j = 0; j < 2; j++) {
                int mm = mcol * 16 + j * 8 + g;
                unsigned b0v = *(const unsigned*)&csl[mm * CST_STR + ks * 16 + 2 * tg];
                unsigned b1v = *(const unsigned*)&csl[mm * CST_STR + ks * 16 + 2 * tg + 8];
                mma_f16(acc[nl][j], a0, a1, a2, a3, b0v, b1v);
            }
        }
    }

    // Epilogue: t2[b0+row][mm][nh*8 .. +7] fp16, one 16B store per (row,mm).
    const int rbase = brow * 16 + g;
    #pragma unroll
    for (int j = 0; j < 2; j++) {
        #pragma unroll
        for (int rs = 0; rs < 2; rs++) {
            #pragma unroll
            for (int ms = 0; ms < 2; ms++) {
                const int row = rbase + rs * 8;
                const int mm  = mcol * 16 + j * 8 + 2 * tg + ms;
                const int e   = rs * 2 + ms;
                uint4 v;
                v.x = pack_h2(acc[0][j][e], acc[1][j][e]);
                v.y = pack_h2(acc[2][j][e], acc[3][j][e]);
                v.z = pack_h2(acc[4][j][e], acc[5][j][e]);
                v.w = pack_h2(acc[6][j][e], acc[7][j][e]);
                *(uint4*)(g_th + (size_t)(b0 + row) * HID + mm * 128 + nh * 8) = v;
            }
        }
    }
}

// ---------------------------------------------------------------------------
// Stage 2: CTA = (128-row btile, one m-block). 256 threads, 8 warps,
// 2 CTAs/SM (inter-CTA overlap hides the prologue load).
// A = t2 rows (fp16, 256B contiguous), B = conn2h[m] ([o][n] fp16).
// smem: As [128][136] + Bs [128][136] fp16 = 69,632B. Stride 136 halves:
// (68*row + tg) % 32 distinct for row=g 0..7 -> conflict-free half2 loads.
// grid = 32 x 64 = 2048 CTAs (6.9 waves at 2/SM).
// ---------------------------------------------------------------------------
#define AS2_STR 136
#define SMEM2   (2 * 128 * AS2_STR * 2)

__global__ void __launch_bounds__(256, 2)
stage2_kernel(float* __restrict__ out) {
    extern __shared__ unsigned char smem_raw[];
    __half* As = (__half*)smem_raw;                 // [128][136]
    __half* Bs = As + 128 * AS2_STR;                // [128][136]

    const int tid = threadIdx.x;
    const int m   = blockIdx.y;
    const int b0  = blockIdx.x * 128;

    const unsigned as_base = (unsigned)__cvta_generic_to_shared(As);
    const unsigned bs_base = (unsigned)__cvta_generic_to_shared(Bs);

    // Prologue: As (t rows) + Bs (conn2h block), one group.
    #pragma unroll
    for (int j = 0; j < 8; j++) {
        int c = tid + j * 256;                      // 2048 chunks of 16B
        int row = c >> 4, c4 = c & 15;
        cp16(as_base + (unsigned)(row * AS2_STR + c4 * 8) * 2,
             g_th + (size_t)(b0 + row) * HID + m * 128 + c4 * 8);
    }
    #pragma unroll
    for (int j = 0; j < 8; j++) {
        int c = tid + j * 256;
        int o = c >> 4, c4 = c & 15;
        cp16(bs_base + (unsigned)(o * AS2_STR + c4 * 8) * 2,
             g_conn2h + ((size_t)m * O2 + o) * I2 + c4 * 8);
    }
    cp_commit();
    cp_wait<0>();
    __syncthreads();

    const int w    = tid >> 5;
    const int lane = tid & 31;
    const int g    = lane >> 2;
    const int tg   = lane & 3;
    const int brow = w & 3;    // rows base 32*brow
    const int ocol = w >> 2;   // o base 64*ocol

    float acc[2][8][4] = {};
    #pragma unroll
    for (int ks = 0; ks < 8; ks++) {               // k = 16 per MMA
        const int k0 = ks * 16 + 2 * tg;
        unsigned a[2][4];
        #pragma unroll
        for (int rt = 0; rt < 2; rt++) {
            int r = brow * 32 + rt * 16 + g;
            a[rt][0] = *(const unsigned*)&As[r * AS2_STR + k0];
            a[rt][1] = *(const unsigned*)&As[(r + 8) * AS2_STR + k0];
            a[rt][2] = *(const unsigned*)&As[r * AS2_STR + k0 + 8];
            a[rt][3] = *(const unsigned*)&As[(r + 8) * AS2_STR + k0 + 8];
        }
        #pragma unroll
        for (int ct = 0; ct < 8; ct++) {
            int o = ocol * 64 + ct * 8 + g;
            unsigned b0v = *(const unsigned*)&Bs[o * AS2_STR + k0];
            unsigned b1v = *(const unsigned*)&Bs[o * AS2_STR + k0 + 8];
            #pragma unroll
            for (int rt = 0; rt < 2; rt++)
                mma_f16(acc[rt][ct], a[rt][0], a[rt][1], a[rt][2], a[rt][3],
                        b0v, b1v);
        }
    }

    // Epilogue: out[b][m*128 + o] fp32.
    #pragma unroll
    for (int rt = 0; rt < 2; rt++) {
        int r = b0 + brow * 32 + rt * 16 + g;
        #pragma unroll
        for (int ct = 0; ct < 8; ct++) {
            int o = m * 128 + ocol * 64 + ct * 8 + 2 * tg;
            *(float2*)(out + (size_t)r * HID + o) =
                make_float2(acc[rt][ct][0], acc[rt][ct][1]);
            *(float2*)(out + (size_t)(r + 8) * HID + o) =
                make_float2(acc[rt][ct][2], acc[rt][ct][3]);
        }
    }
}

// ---------------------------------------------------------------------------
// launch
// ---------------------------------------------------------------------------
extern "C" void kernel_launch(void* const* d_in, const int* in_sizes, int n_in,
                              void* d_out, int out_size) {
    const float* x  = (const float*)d_in[0];
    const float* c1 = (const float*)d_in[1];
    const float* c2 = (const float*)d_in[2];
    float* out = (float*)d_out;
    const int B = in_sizes[0] / HID;   // 4096

    cudaFuncSetAttribute(stage1_kernel,
                         cudaFuncAttributeMaxDynamicSharedMemorySize, SMEM1);
    cudaFuncSetAttribute(stage2_kernel,
                         cudaFuncAttributeMaxDynamicSharedMemorySize, SMEM2);

    softmax_kernel<<<(NB1 * M1 + NB2 * O2) / 128, 128>>>(c1, c2);
    stage1_kernel<<<dim3(B / S1_BT, 16), 256, SMEM1>>>(x);
    stage2_kernel<<<dim3(B / 128, NB2), 256, SMEM2>>>(out);
}

// round 17
// speedup vs baseline: 2.1668x; 1.0876x over previous
#include <cuda_runtime.h>
#include <cuda_fp16.h>
#include <cstdint>
#include <cstddef>

// ---------------------------------------------------------------------------
// Monarch-like two-stage block-diagonal interconnect, softmax-gated.
//   conn1 = softmax(c1*3, axis=i)   c1: [128][64][64]  ([n][i][m])
//   conn2 = softmax(c2*3, axis=n)   c2: [64][128][128] ([m][n][o])
//   t[b,n,m]   = sum_i x[b, n*64+i] * conn1[n,i,m]
//   out[b,m,o] = sum_n t[b,n,m]     * conn2[m,n,o]
//
// fp16 datapath (tf32-equivalent mantissa), fp32 accumulation, legacy
// mma.m16n8k16 (tcgen05 unavailable: harness PTX targets compute_103,
// which rejects all arch-specific tcgen05 instructions).
//
// NEW this round: software pipeline across 4 batch chunks. stage1 chain on
// the capture (NULL) stream, stage2 chain on a forked side stream; stage2
// chunk c waits on an event recorded after stage1 chunk c. Softmax is split
// so conn2's softmax overlaps stage1 chunk 0.
// ---------------------------------------------------------------------------

#define HID     8192
#define NB1     128
#define I1      64
#define M1      64
#define NB2     64
#define I2      128
#define O2      128
#define MAXB    4096
#define NCHUNK  4

__device__ __half g_conn1h[NB1 * M1 * I1];      // [n][m][i]
__device__ __half g_conn2h[NB2 * O2 * I2];      // [m][o][n]
__device__ __half g_th[(size_t)MAXB * HID];     // t2: [b][m][n]

// ---------------------------------------------------------------------------
// helpers
// ---------------------------------------------------------------------------
__device__ __forceinline__ unsigned pack_h2(float lo, float hi) {
    unsigned u;
    asm("cvt.rn.f16x2.f32 %0, %1, %2;" : "=r"(u) : "f"(hi), "f"(lo));
    return u;
}

__device__ __forceinline__ void mma_f16(float* d,
                                        unsigned a0, unsigned a1,
                                        unsigned a2, unsigned a3,
                                        unsigned b0, unsigned b1) {
    asm volatile(
        "mma.sync.aligned.m16n8k16.row.col.f32.f16.f16.f32 "
        "{%0,%1,%2,%3}, {%4,%5,%6,%7}, {%8,%9}, {%0,%1,%2,%3};\n"
        : "+f"(d[0]), "+f"(d[1]), "+f"(d[2]), "+f"(d[3])
        : "r"(a0), "r"(a1), "r"(a2), "r"(a3), "r"(b0), "r"(b1));
}

__device__ __forceinline__ void cp16(unsigned smem_addr, const void* gptr) {
    asm volatile("cp.async.cg.shared.global [%0], [%1], 16;"
                 :: "r"(smem_addr), "l"(gptr));
}
__device__ __forceinline__ void cp_commit() {
    asm volatile("cp.async.commit_group;");
}
template <int N> __device__ __forceinline__ void cp_wait() {
    asm volatile("cp.async.wait_group %0;" :: "n"(N));
}

// ---------------------------------------------------------------------------
// Softmax precompute, split in two so softmax2 can overlap stage1 chunk 0.
// One global read pass, column in registers, fp16 TRANSPOSED outputs.
// ---------------------------------------------------------------------------
__global__ void __launch_bounds__(128)
softmax1_kernel(const float* __restrict__ c1) {
    int gid = blockIdx.x * blockDim.x + threadIdx.x;   // 8192
    int n = gid >> 6, m = gid & 63;
    const float* p = c1 + (size_t)n * (I1 * M1) + m;
    float v[I1];
    float mx = -1e30f;
    #pragma unroll
    for (int i = 0; i < I1; i++) {
        v[i] = p[i * M1] * 3.0f;
        mx = fmaxf(mx, v[i]);
    }
    float s = 0.0f;
    #pragma unroll
    for (int i = 0; i < I1; i++) {
        v[i] = expf(v[i] - mx);
        s += v[i];
    }
    float inv = 1.0f / s;
    unsigned u[I1 / 2];
    #pragma unroll
    for (int i = 0; i < I1 / 2; i++)
        u[i] = pack_h2(v[2 * i] * inv, v[2 * i + 1] * inv);
    uint4* q = (uint4*)(g_conn1h + ((size_t)n * M1 + m) * I1);
    #pragma unroll
    for (int i = 0; i < I1 / 8; i++)
        q[i] = make_uint4(u[4 * i], u[4 * i + 1], u[4 * i + 2], u[4 * i + 3]);
}

__global__ void __launch_bounds__(128)
softmax2_kernel(const float* __restrict__ c2) {
    int gid = blockIdx.x * blockDim.x + threadIdx.x;   // 8192
    int m = gid >> 7, o = gid & 127;
    const float* p = c2 + (size_t)m * (I2 * O2) + o;
    float v[I2];
    float mx = -1e30f;
    #pragma unroll
    for (int i = 0; i < I2; i++) {
        v[i] = p[i * O2] * 3.0f;
        mx = fmaxf(mx, v[i]);
    }
    float s = 0.0f;
    #pragma unroll
    for (int i = 0; i < I2; i++) {
        v[i] = expf(v[i] - mx);
        s += v[i];
    }
    float inv = 1.0f / s;
    unsigned u[I2 / 2];
    #pragma unroll
    for (int i = 0; i < I2 / 2; i++)
        u[i] = pack_h2(v[2 * i] * inv, v[2 * i + 1] * inv);
    uint4* q = (uint4*)(g_conn2h + ((size_t)m * O2 + o) * I2);
    #pragma unroll
    for (int i = 0; i < I2 / 8; i++)
        q[i] = make_uint4(u[4 * i], u[4 * i + 1], u[4 * i + 2], u[4 * i + 3]);
}

// ---------------------------------------------------------------------------
// Stage 1: CTA = (32-row btile, group of 8 n-blocks). 256 threads, 8 warps,
// 2 CTAs/SM. x fp32 in smem (A-frags via LDS.64 + cvt.rn.f16x2); conn1h
// fp16 in a 4-slot ring, prefetch distance 3, one barrier/iter.
// smem: xs f32 [32][520] + cst f16 [4][64][72] = 103,424 B.
// ---------------------------------------------------------------------------
#define S1_BT    32
#define XS_STR   520
#define CST_STR  72
#define CS_SLOTS 4
#define SMEM1    (S1_BT * XS_STR * 4 + CS_SLOTS * M1 * CST_STR * 2)

__global__ void __launch_bounds__(256, 2)
stage1_kernel(const float* __restrict__ x, int b_base) {
    extern __shared__ unsigned char smem_raw[];
    float*  xs  = (float*)smem_raw;                       // [32][520]
    __half* cst = (__half*)(xs + S1_BT * XS_STR);         // [4][64][72]

    const int tid = threadIdx.x;
    const int bt  = blockIdx.x;
    const int nh  = blockIdx.y;            // 0..15
    const int b0  = b_base + bt * S1_BT;

    const unsigned xs_base  = (unsigned)__cvta_generic_to_shared(xs);
    const unsigned cst_base = (unsigned)__cvta_generic_to_shared(cst);

    auto issue_group = [&](int k) {
        #pragma unroll
        for (int j = 0; j < 2; j++) {
            int c = tid + j * 256;
            int row = c >> 4, c4 = c & 15;
            const float* src = x + (size_t)(b0 + row) * HID
                                 + (size_t)nh * 512 + k * 64 + c4 * 4;
            cp16(xs_base + (unsigned)(row * XS_STR + k * 64 + c4 * 4) * 4, src);
        }
        int n = nh * 8 + k, slot = k & (CS_SLOTS - 1);
        #pragma unroll
        for (int j = 0; j < 2; j++) {
            int c = tid + j * 256;
            int row = c >> 3, c8 = c & 7;
            const __half* src = g_conn1h + ((size_t)n * M1 + row) * I1 + c8 * 8;
            cp16(cst_base + (unsigned)(slot * M1 * CST_STR + row * CST_STR + c8 * 8) * 2,
                 src);
        }
        cp_commit();
    };

    issue_group(0);
    issue_group(1);
    issue_group(2);

    const int w    = tid >> 5;
    const int lane = tid & 31;
    const int g    = lane >> 2;
    const int tg   = lane & 3;
    const int brow = w >> 2;
    const int mcol = w & 3;

    float acc[8][2][4] = {};

    #pragma unroll
    for (int nl = 0; nl < 8; nl++) {
        if (nl < 6)       cp_wait<2>();
        else if (nl == 6) cp_wait<1>();
        else              cp_wait<0>();
        __syncthreads();
        if (nl + 3 < 8) issue_group(nl + 3);

        const __half* csl = cst + (nl & (CS_SLOTS - 1)) * M1 * CST_STR;
        #pragma unroll
        for (int ks = 0; ks < 4; ks++) {
            const int xc = nl * 64 + ks * 16 + 2 * tg;
            const int r  = brow * 16 + g;
            float2 f0 = *(const float2*)&xs[r * XS_STR + xc];
            float2 f1 = *(const float2*)&xs[(r + 8) * XS_STR + xc];
            float2 f2 = *(const float2*)&xs[r * XS_STR + xc + 8];
            float2 f3 = *(const float2*)&xs[(r + 8) * XS_STR + xc + 8];
            unsigned a0 = pack_h2(f0.x, f0.y);
            unsigned a1 = pack_h2(f1.x, f1.y);
            unsigned a2 = pack_h2(f2.x, f2.y);
            unsigned a3 = pack_h2(f3.x, f3.y);
            #pragma unroll
            for (int j = 0; j < 2; j++) {
                int mm = mcol * 16 + j * 8 + g;
                unsigned b0v = *(const unsigned*)&csl[mm * CST_STR + ks * 16 + 2 * tg];
                unsigned b1v = *(const unsigned*)&csl[mm * CST_STR + ks * 16 + 2 * tg + 8];
                mma_f16(acc[nl][j], a0, a1, a2, a3, b0v, b1v);
            }
        }
    }

    // Epilogue: t2[b0+row][mm][nh*8 .. +7] fp16, one 16B store per (row,mm).
    const int rbase = brow * 16 + g;
    #pragma unroll
    for (int j = 0; j < 2; j++) {
        #pragma unroll
        for (int rs = 0; rs < 2; rs++) {
            #pragma unroll
            for (int ms = 0; ms < 2; ms++) {
                const int row = rbase + rs * 8;
                const int mm  = mcol * 16 + j * 8 + 2 * tg + ms;
                const int e   = rs * 2 + ms;
                uint4 v;
                v.x = pack_h2(acc[0][j][e], acc[1][j][e]);
                v.y = pack_h2(acc[2][j][e], acc[3][j][e]);
                v.z = pack_h2(acc[4][j][e], acc[5][j][e]);
                v.w = pack_h2(acc[6][j][e], acc[7][j][e]);
                *(uint4*)(g_th + (size_t)(b0 + row) * HID + mm * 128 + nh * 8) = v;
            }
        }
    }
}

// ---------------------------------------------------------------------------
// Stage 2: CTA = (128-row btile, one m-block). 256 threads, 8 warps,
// 2 CTAs/SM. A = t2 rows (fp16, 256B contiguous), B = conn2h[m] ([o][n]).
// smem: As [128][136] + Bs [128][136] fp16 = 69,632 B.
// ---------------------------------------------------------------------------
#define AS2_STR 136
#define SMEM2   (2 * 128 * AS2_STR * 2)

__global__ void __launch_bounds__(256, 2)
stage2_kernel(float* __restrict__ out, int b_base) {
    extern __shared__ unsigned char smem_raw[];
    __half* As = (__half*)smem_raw;                 // [128][136]
    __half* Bs = As + 128 * AS2_STR;                // [128][136]

    const int tid = threadIdx.x;
    const int m   = blockIdx.y;
    const int b0  = b_base + blockIdx.x * 128;

    const unsigned as_base = (unsigned)__cvta_generic_to_shared(As);
    const unsigned bs_base = (unsigned)__cvta_generic_to_shared(Bs);

    #pragma unroll
    for (int j = 0; j < 8; j++) {
        int c = tid + j * 256;                      // 2048 chunks of 16B
        int row = c >> 4, c4 = c & 15;
        cp16(as_base + (unsigned)(row * AS2_STR + c4 * 8) * 2,
             g_th + (size_t)(b0 + row) * HID + m * 128 + c4 * 8);
    }
    #pragma unroll
    for (int j = 0; j < 8; j++) {
        int c = tid + j * 256;
        int o = c >> 4, c4 = c & 15;
        cp16(bs_base + (unsigned)(o * AS2_STR + c4 * 8) * 2,
             g_conn2h + ((size_t)m * O2 + o) * I2 + c4 * 8);
    }
    cp_commit();
    cp_wait<0>();
    __syncthreads();

    const int w    = tid >> 5;
    const int lane = tid & 31;
    const int g    = lane >> 2;
    const int tg   = lane & 3;
    const int brow = w & 3;    // rows base 32*brow
    const int ocol = w >> 2;   // o base 64*ocol

    float acc[2][8][4] = {};
    #pragma unroll
    for (int ks = 0; ks < 8; ks++) {               // k = 16 per MMA
        const int k0 = ks * 16 + 2 * tg;
        unsigned a[2][4];
        #pragma unroll
        for (int rt = 0; rt < 2; rt++) {
            int r = brow * 32 + rt * 16 + g;
            a[rt][0] = *(const unsigned*)&As[r * AS2_STR + k0];
            a[rt][1] = *(const unsigned*)&As[(r + 8) * AS2_STR + k0];
            a[rt][2] = *(const unsigned*)&As[r * AS2_STR + k0 + 8];
            a[rt][3] = *(const unsigned*)&As[(r + 8) * AS2_STR + k0 + 8];
        }
        #pragma unroll
        for (int ct = 0; ct < 8; ct++) {
            int o = ocol * 64 + ct * 8 + g;
            unsigned b0v = *(const unsigned*)&Bs[o * AS2_STR + k0];
            unsigned b1v = *(const unsigned*)&Bs[o * AS2_STR + k0 + 8];
            #pragma unroll
            for (int rt = 0; rt < 2; rt++)
                mma_f16(acc[rt][ct], a[rt][0], a[rt][1], a[rt][2], a[rt][3],
                        b0v, b1v);
        }
    }

    #pragma unroll
    for (int rt = 0; rt < 2; rt++) {
        int r = b0 + brow * 32 + rt * 16 + g;
        #pragma unroll
        for (int ct = 0; ct < 8; ct++) {
            int o = m * 128 + ocol * 64 + ct * 8 + 2 * tg;
            *(float2*)(out + (size_t)r * HID + o) =
                make_float2(acc[rt][ct][0], acc[rt][ct][1]);
            *(float2*)(out + (size_t)(r + 8) * HID + o) =
                make_float2(acc[rt][ct][2], acc[rt][ct][3]);
        }
    }
}

// ---------------------------------------------------------------------------
// launch: 4-chunk software pipeline via stream fork/join (graph-capturable).
// Stream/events created once on the first (uncaptured) correctness call.
// ---------------------------------------------------------------------------
extern "C" void kernel_launch(void* const* d_in, const int* in_sizes, int n_in,
                              void* d_out, int out_size) {
    const float* x  = (const float*)d_in[0];
    const float* c1 = (const float*)d_in[1];
    const float* c2 = (const float*)d_in[2];
    float* out = (float*)d_out;
    const int B = in_sizes[0] / HID;   // 4096
    const int chunk = B / NCHUNK;      // 1024

    static bool inited = false;
    static cudaStream_t side = nullptr;
    static cudaEvent_t evFork, evS1[NCHUNK], evJoin;
    if (!inited) {
        cudaFuncSetAttribute(stage1_kernel,
                             cudaFuncAttributeMaxDynamicSharedMemorySize, SMEM1);
        cudaFuncSetAttribute(stage2_kernel,
                             cudaFuncAttributeMaxDynamicSharedMemorySize, SMEM2);
        cudaStreamCreateWithFlags(&side, cudaStreamNonBlocking);
        cudaEventCreateWithFlags(&evFork, cudaEventDisableTiming);
        for (int c = 0; c < NCHUNK; c++)
            cudaEventCreateWithFlags(&evS1[c], cudaEventDisableTiming);
        cudaEventCreateWithFlags(&evJoin, cudaEventDisableTiming);
        inited = true;
    }

    if (side) {
        // Fork side stream off the capture (NULL) stream.
        cudaEventRecord(evFork, 0);
        cudaStreamWaitEvent(side, evFork, 0);

        // conn1 softmax heads the stage1 chain; conn2 softmax overlaps it.
        softmax1_kernel<<<(NB1 * M1) / 128, 128, 0, 0>>>(c1);
        softmax2_kernel<<<(NB2 * O2) / 128, 128, 0, side>>>(c2);

        for (int c = 0; c < NCHUNK; c++) {
            stage1_kernel<<<dim3(chunk / S1_BT, 16), 256, SMEM1, 0>>>(
                x, c * chunk);
            cudaEventRecord(evS1[c], 0);
            cudaStreamWaitEvent(side, evS1[c], 0);
            stage2_kernel<<<dim3(chunk / 128, NB2), 256, SMEM2, side>>>(
                out, c * chunk);
        }

        // Join side stream back into the capture stream.
        cudaEventRecord(evJoin, side);
        cudaStreamWaitEvent(0, evJoin, 0);
    } else {
        // Fallback: serial on the capture stream.
        softmax1_kernel<<<(NB1 * M1) / 128, 128>>>(c1);
        softmax2_kernel<<<(NB2 * O2) / 128, 128>>>(c2);
        stage1_kernel<<<dim3(B / S1_BT, 16), 256, SMEM1>>>(x, 0);
        stage2_kernel<<<dim3(B / 128, NB2), 256, SMEM2>>>(out, 0);
    }
}